// round 15
// baseline (speedup 1.0000x reference)
#include <cuda_runtime.h>
#include <cuda_fp16.h>
#include <math.h>
#include <stdint.h>

#define BATCH 4
#define SEQ   2048
#define DM    1024
#define NH    16
#define DH    64
#define DFF   4096
#define BS    (BATCH*SEQ)
#define QKVS  3072
#define EPSLN 1e-5f
#define CEXP  0.1803368801f   // log2(e)/8

// ---------------- scratch ----------------
__device__ float g_resid[(size_t)BS*DM];
__device__ __half g_n[(size_t)BS*DM];
__device__ __half g_qkv[(size_t)BS*QKVS];
__device__ __half g_a[(size_t)BS*DM];
__device__ __half g_h[(size_t)BS*DFF];
#define WOFF_Q  ((size_t)0)
#define WOFF_K  ((size_t)DM*DM)
#define WOFF_V  ((size_t)2*DM*DM)
#define WOFF_O  ((size_t)3*DM*DM)
#define WOFF_F1 ((size_t)4*DM*DM)
#define WOFF_F2 ((size_t)(4*DM*DM) + (size_t)DFF*DM)
__device__ __half g_w[(size_t)4*DM*DM + 2*(size_t)DFF*DM];

// ---------------- helpers ----------------
__device__ __forceinline__ uint32_t smem_u32(const void* p) {
    uint32_t a;
    asm("{ .reg .u64 t; cvta.to.shared.u64 t, %1; cvt.u32.u64 %0, t; }" : "=r"(a) : "l"(p));
    return a;
}
__device__ __forceinline__ uint32_t swz128(uint32_t off) { return off ^ ((off >> 3) & 0x70); }

__device__ __forceinline__ void ldsm_x4(uint32_t addr, uint32_t& r0, uint32_t& r1,
                                        uint32_t& r2, uint32_t& r3) {
    asm volatile("ldmatrix.sync.aligned.m8n8.x4.shared.b16 {%0,%1,%2,%3}, [%4];"
                 : "=r"(r0), "=r"(r1), "=r"(r2), "=r"(r3) : "r"(addr));
}
__device__ __forceinline__ void ldsm_x4t(uint32_t addr, uint32_t* r) {
    asm volatile("ldmatrix.sync.aligned.m8n8.x4.trans.shared.b16 {%0,%1,%2,%3}, [%4];"
                 : "=r"(r[0]), "=r"(r[1]), "=r"(r[2]), "=r"(r[3]) : "r"(addr));
}
__device__ __forceinline__ void mma_f16(float* d, uint32_t a0, uint32_t a1,
                                        uint32_t a2, uint32_t a3,
                                        uint32_t b0, uint32_t b1) {
    asm volatile("mma.sync.aligned.m16n8k16.row.col.f32.f16.f16.f32 "
                 "{%0,%1,%2,%3}, {%4,%5,%6,%7}, {%8,%9}, {%0,%1,%2,%3};"
                 : "+f"(d[0]), "+f"(d[1]), "+f"(d[2]), "+f"(d[3])
                 : "r"(a0), "r"(a1), "r"(a2), "r"(a3), "r"(b0), "r"(b1));
}
#define CPA(dst, src) asm volatile("cp.async.cg.shared.global [%0], [%1], 16;" :: "r"(dst), "l"(src))

__device__ __forceinline__ float gelu_f(float x) {
    float c = x * x * x;
    float t = tanhf(0.7978845608f * (x + 0.044715f * c));
    return 0.5f * x * (1.0f + t);
}
__device__ __forceinline__ uint32_t packh2(float x, float y) {
    __half2 h = __floats2half2_rn(x, y);
    return *reinterpret_cast<uint32_t*>(&h);
}
__device__ __forceinline__ float exp2p(float x) {
    x = fmaxf(x, -60.0f);
    float y = x + 12582912.0f;
    int   n = __float_as_int(y) - 0x4B400000;
    float f = x - (y - 12582912.0f);
    float p =            1.3333558e-3f;
    p = fmaf(p, f, 9.6181291e-3f);
    p = fmaf(p, f, 5.5504109e-2f);
    p = fmaf(p, f, 2.4022651e-1f);
    p = fmaf(p, f, 6.9314718e-1f);
    p = fmaf(p, f, 1.0f);
    return __uint_as_float(__float_as_uint(p) + ((uint32_t)n << 23));
}

// ---------------- fused weight convert (4 float4 per thread for MLP) ----------------
__global__ __launch_bounds__(256)
void conv_all(const float* __restrict__ wq, const float* __restrict__ wk,
              const float* __restrict__ wv, const float* __restrict__ wo,
              const float* __restrict__ f1, const float* __restrict__ f2,
              __half* __restrict__ w) {
    int base = (blockIdx.x * 256 + threadIdx.x) * 4;   // 4 consecutive float4 slots
    float4 v[4];
    #pragma unroll
    for (int j = 0; j < 4; j++) {
        int i = base + j;
        const float* src;
        int loc;
        if (i < (1 << 20)) {
            int r = i >> 18;
            loc = i & ((1 << 18) - 1);
            src = (r == 0) ? wq : (r == 1) ? wk : (r == 2) ? wv : wo;
        } else {
            int jj = i - (1 << 20);
            if (jj < (1 << 20)) { src = f1; loc = jj; }
            else                { src = f2; loc = jj - (1 << 20); }
        }
        v[j] = *(const float4*)(src + (size_t)loc * 4);
    }
    #pragma unroll
    for (int j = 0; j < 4; j++) {
        uint2 o;
        o.x = packh2(v[j].x, v[j].y);
        o.y = packh2(v[j].z, v[j].w);
        *(uint2*)(w + (size_t)(base + j) * 4) = o;
    }
}

// ---------------- layernorm -> f16 ----------------
__global__ __launch_bounds__(256)
void layernorm_k(const float* __restrict__ x, const float* __restrict__ gamma,
                 const float* __restrict__ beta, __half* __restrict__ oh) {
    int row = blockIdx.x;
    const float* xr = x + (size_t)row * DM;
    int t = threadIdx.x;
    float4 v = *(const float4*)(xr + t * 4);
    float s  = v.x + v.y + v.z + v.w;
    float ss = v.x*v.x + v.y*v.y + v.z*v.z + v.w*v.w;
    #pragma unroll
    for (int o = 16; o > 0; o >>= 1) {
        s  += __shfl_xor_sync(0xffffffffu, s,  o);
        ss += __shfl_xor_sync(0xffffffffu, ss, o);
    }
    __shared__ float rs[8], rss[8];
    int w = t >> 5, l = t & 31;
    if (l == 0) { rs[w] = s; rss[w] = ss; }
    __syncthreads();
    if (w == 0) {
        float a = (l < 8) ? rs[l]  : 0.f;
        float b = (l < 8) ? rss[l] : 0.f;
        #pragma unroll
        for (int o = 4; o > 0; o >>= 1) {
            a += __shfl_xor_sync(0xffffffffu, a, o);
            b += __shfl_xor_sync(0xffffffffu, b, o);
        }
        if (l == 0) { rs[0] = a; rss[0] = b; }
    }
    __syncthreads();
    float mean = rs[0] * (1.0f / DM);
    float var  = rss[0] * (1.0f / DM) - mean * mean;
    float rstd = rsqrtf(var + EPSLN);
    float4 gv = *(const float4*)(gamma + t * 4);
    float4 bv = *(const float4*)(beta  + t * 4);
    uint2 o2;
    o2.x = packh2(gv.x * ((v.x - mean) * rstd) + bv.x,
                  gv.y * ((v.y - mean) * rstd) + bv.y);
    o2.y = packh2(gv.z * ((v.z - mean) * rstd) + bv.z,
                  gv.w * ((v.w - mean) * rstd) + bv.w);
    *(uint2*)(oh + (size_t)row * DM + t * 4) = o2;
}

// ---------------- fp16 GEMM NT: 256x128 CTA tile, 512 threads, 16 warps ----------------
// Warp grid 4x4, warp tile 64x32 (same inner loop as proven R10 config).
// K-chunk 64, 3-stage cp.async. Stage = A(32KB) + B(16KB) = 48KB.
#define GSTG 49152
#define GSM  (3*GSTG + 1024)

template<int EPI, int OUT>
__global__ __launch_bounds__(512, 1)
void gemm_tc(const __half* __restrict__ A_, const __half* __restrict__ W_,
             const float* __restrict__ R, float* __restrict__ Cf,
             __half* __restrict__ Ch, int M, int N, int K) {
    extern __shared__ char dsm[];
    uint32_t sb = (smem_u32(dsm) + 1023) & ~1023u;

    int tid = threadIdx.x, wid = tid >> 5, lane = tid & 31;
    int wm = wid >> 2, wn = wid & 3;           // rows wm*64, cols wn*32

    const char* Ab = (const char*)(A_ + (size_t)blockIdx.y * 256 * K);
    const char* Wb = (const char*)(W_ + (size_t)blockIdx.x * 128 * K);

    int cs = tid & 7;
    int rbase = tid >> 3;                      // 0..63
    uint32_t soA[4]; size_t gbA[4];            // A rows rbase + 64*i
    uint32_t soB[2]; size_t gbB[2];            // B rows rbase + 64*i
    #pragma unroll
    for (int i = 0; i < 4; i++) {
        int row = rbase + 64 * i;
        soA[i] = swz128(row * 128 + cs * 16);
        gbA[i] = (size_t)row * K * 2 + cs * 16;
    }
    #pragma unroll
    for (int i = 0; i < 2; i++) {
        int row = rbase + 64 * i;
        soB[i] = swz128(row * 128 + cs * 16);
        gbB[i] = (size_t)row * K * 2 + cs * 16;
    }

    #define G_ISSUE(kb, st) do { \
        uint32_t s_ = sb + (st) * GSTG; \
        size_t kbb = (size_t)(kb) * 2; \
        _Pragma("unroll") \
        for (int i_ = 0; i_ < 4; i_++) \
            CPA(s_ + soA[i_], Ab + gbA[i_] + kbb); \
        _Pragma("unroll") \
        for (int i_ = 0; i_ < 2; i_++) \
            CPA(s_ + 32768 + soB[i_], Wb + gbB[i_] + kbb); \
    } while (0)

    float acc[4][4][4];
    #pragma unroll
    for (int i = 0; i < 4; i++)
        #pragma unroll
        for (int j = 0; j < 4; j++)
            #pragma unroll
            for (int e = 0; e < 4; e++) acc[i][j][e] = 0.f;

    int g = lane >> 3, rg = lane & 7;
    int nch = K >> 6;

    G_ISSUE(0, 0);
    asm volatile("cp.async.commit_group;");
    G_ISSUE(64, 1);
    asm volatile("cp.async.commit_group;");

    int st_c = 0, st_i = 2;
    for (int ch = 0; ch < nch; ch++) {
        if (ch + 1 < nch) asm volatile("cp.async.wait_group 1;" ::: "memory");
        else              asm volatile("cp.async.wait_group 0;" ::: "memory");
        __syncthreads();
        if (ch + 2 < nch) {
            G_ISSUE((ch + 2) << 6, st_i);
            asm volatile("cp.async.commit_group;");
            st_i = (st_i == 2) ? 0 : st_i + 1;
        }
        uint32_t ah = sb + st_c * GSTG;
        st_c = (st_c == 2) ? 0 : st_c + 1;
        uint32_t bh = ah + 32768;

        #pragma unroll
        for (int ks = 0; ks < 4; ks++) {
            int kcol = ks * 32 + (g >> 1) * 16;
            uint32_t bhr[2][4];
            #pragma unroll
            for (int p = 0; p < 2; p++) {
                int nrow = wn * 32 + p * 16 + (g & 1) * 8 + rg;
                uint32_t off = swz128(nrow * 128 + kcol);
                ldsm_x4(bh + off, bhr[p][0], bhr[p][1], bhr[p][2], bhr[p][3]);
            }
            #pragma unroll
            for (int mf = 0; mf < 4; mf++) {
                int arow = wm * 64 + mf * 16 + (g & 1) * 8 + rg;
                uint32_t off = swz128(arow * 128 + kcol);
                uint32_t a0,a1,a2,a3;
                ldsm_x4(ah + off, a0, a1, a2, a3);
                #pragma unroll
                for (int nf = 0; nf < 4; nf++) {
                    int p = nf >> 1, q = nf & 1;
                    mma_f16(acc[mf][nf], a0, a1, a2, a3, bhr[p][q], bhr[p][q + 2]);
                }
            }
        }
    }

    #pragma unroll
    for (int mf = 0; mf < 4; mf++) {
        #pragma unroll
        for (int h = 0; h < 2; h++) {
            size_t row = (size_t)blockIdx.y * 256 + wm * 64 + mf * 16 + (lane >> 2) + h * 8;
            #pragma unroll
            for (int nf = 0; nf < 4; nf++) {
                size_t col = (size_t)blockIdx.x * 128 + wn * 32 + nf * 8 + (lane & 3) * 2;
                float o0 = acc[mf][nf][h * 2 + 0];
                float o1 = acc[mf][nf][h * 2 + 1];
                if (EPI == 1) {
                    float2 r2 = *(const float2*)(R + row * N + col);
                    o0 += r2.x; o1 += r2.y;
                }
                if (EPI == 2) { o0 = gelu_f(o0); o1 = gelu_f(o1); }
                if (OUT == 0) {
                    *(float2*)(Cf + row * N + col) = make_float2(o0, o1);
                } else {
                    *(uint32_t*)(Ch + row * N + col) = packh2(o0, o1);
                }
            }
        }
    }
}

// ---------------- fp16 flash attention (R14: 64-row Q tile, hoisted offsets) ----------------
#define ASM (8192 + 3*16384 + 1024)

__global__ __launch_bounds__(128)
void flash_attn_tc(const __half* __restrict__ QKV, __half* __restrict__ O) {
    extern __shared__ char dsm[];
    uint32_t sb = (smem_u32(dsm) + 1023) & ~1023u;
    uint32_t sQ = sb;

    int qt = gridDim.x - 1 - blockIdx.x;
    int bh = blockIdx.y;
    int b = bh >> 4, h = bh & 15;
    int tid = threadIdx.x, w = tid >> 5, lane = tid & 31;
    int g = lane >> 3, rg = lane & 7;
    int qstart = qt * 64;

    const char* Qc = (const char*)QKV;

    size_t qg = ((size_t)(b * SEQ + qstart)) * QKVS + h * 64;
    #pragma unroll
    for (int i = 0; i < 4; i++) {
        int seg = tid + i * 128;
        int row = seg >> 3, cs = seg & 7;
        uint32_t so = swz128(row * 128 + cs * 16);
        size_t gb = (qg + (size_t)row * QKVS + cs * 8) * 2;
        CPA(sQ + so, Qc + gb);
    }

    #define AKV_ISSUE(kbase, st) do { \
        uint32_t s_ = sb + 8192 + (st) * 16384; \
        size_t g0 = ((size_t)(b * SEQ + (kbase))) * QKVS + 1024 + h * 64; \
        _Pragma("unroll") \
        for (int i_ = 0; i_ < 4; i_++) { \
            int seg_ = tid + i_ * 128; \
            int row_ = seg_ >> 3, cs_ = seg_ & 7; \
            uint32_t so_ = swz128(row_ * 128 + cs_ * 16); \
            size_t gb_ = (g0 + (size_t)row_ * QKVS + cs_ * 8) * 2; \
            CPA(s_ + so_,        Qc + gb_); \
            CPA(s_ + 8192 + so_, Qc + gb_ + 2048); \
        } \
    } while (0)

    AKV_ISSUE(0, 0);
    asm volatile("cp.async.commit_group;");
    if (qt >= 1) {
        AKV_ISSUE(64, 1);
        asm volatile("cp.async.commit_group;");
    }

    uint32_t koff[4][4], voff[4][4];
    #pragma unroll
    for (int kseg = 0; kseg < 4; kseg++) {
        int kcol = kseg * 32 + (g >> 1) * 16;
        #pragma unroll
        for (int p = 0; p < 4; p++) {
            int nrow = p * 16 + (g & 1) * 8 + rg;
            koff[kseg][p] = swz128(nrow * 128 + kcol);
        }
    }
    #pragma unroll
    for (int kk = 0; kk < 4; kk++) {
        int vrow = kk * 16 + (g >> 1) * 8 + rg;
        #pragma unroll
        for (int ep = 0; ep < 4; ep++) {
            int ecol = ep * 16 + (g & 1) * 8;
            voff[kk][ep] = swz128(vrow * 128 + ecol * 2);
        }
    }

    float s[8][4], o[8][4];
    uint32_t qf[4][4];
    #pragma unroll
    for (int nf = 0; nf < 8; nf++)
        #pragma unroll
        for (int e = 0; e < 4; e++) o[nf][e] = 0.f;
    float m0 = -1e30f, m1 = -1e30f, l0 = 0.f, l1 = 0.f;

    int st_c = 0, st_i = 2;
    for (int kb = 0; kb <= qt; kb++) {
        if (kb < qt) asm volatile("cp.async.wait_group 1;" ::: "memory");
        else         asm volatile("cp.async.wait_group 0;" ::: "memory");
        __syncthreads();
        if (kb + 2 <= qt) {
            AKV_ISSUE((kb + 2) * 64, st_i);
            asm volatile("cp.async.commit_group;");
            st_i = (st_i == 2) ? 0 : st_i + 1;
        }

        if (kb == 0) {
            #pragma unroll
            for (int kseg = 0; kseg < 4; kseg++) {
                int arow = w * 16 + (g & 1) * 8 + rg;
                uint32_t off = swz128(arow * 128 + kseg * 32 + (g >> 1) * 16);
                ldsm_x4(sQ + off, qf[kseg][0], qf[kseg][1], qf[kseg][2], qf[kseg][3]);
            }
        }

        uint32_t kB = sb + 8192 + st_c * 16384;
        st_c = (st_c == 2) ? 0 : st_c + 1;
        uint32_t sK = kB, sV = kB + 8192;

        #pragma unroll
        for (int nf = 0; nf < 8; nf++)
            #pragma unroll
            for (int e = 0; e < 4; e++) s[nf][e] = 0.f;
        #pragma unroll
        for (int kseg = 0; kseg < 4; kseg++) {
            uint32_t kh[4][4];
            #pragma unroll
            for (int p = 0; p < 4; p++)
                ldsm_x4(sK + koff[kseg][p], kh[p][0], kh[p][1], kh[p][2], kh[p][3]);
            #pragma unroll
            for (int p = 0; p < 4; p++)
                #pragma unroll
                for (int q = 0; q < 2; q++)
                    mma_f16(s[2*p+q], qf[kseg][0], qf[kseg][1], qf[kseg][2], qf[kseg][3],
                            kh[p][q], kh[p][q + 2]);
        }

        if (kb == qt) {
            int r0 = w * 16 + (lane >> 2);
            int c0 = (lane & 3) * 2;
            #pragma unroll
            for (int nf = 0; nf < 8; nf++) {
                int c = c0 + nf * 8;
                if (c     > r0)     s[nf][0] = -1e30f;
                if (c + 1 > r0)     s[nf][1] = -1e30f;
                if (c     > r0 + 8) s[nf][2] = -1e30f;
                if (c + 1 > r0 + 8) s[nf][3] = -1e30f;
            }
        }

        float mr0 = -1e30f, mr1 = -1e30f;
        #pragma unroll
        for (int nf = 0; nf < 8; nf++) {
            mr0 = fmaxf(mr0, fmaxf(s[nf][0], s[nf][1]));
            mr1 = fmaxf(mr1, fmaxf(s[nf][2], s[nf][3]));
        }
        mr0 = fmaxf(mr0, __shfl_xor_sync(0xffffffffu, mr0, 1));
        mr0 = fmaxf(mr0, __shfl_xor_sync(0xffffffffu, mr0, 2));
        mr1 = fmaxf(mr1, __shfl_xor_sync(0xffffffffu, mr1, 1));
        mr1 = fmaxf(mr1, __shfl_xor_sync(0xffffffffu, mr1, 2));
        if (__any_sync(0xffffffffu, mr0 > m0 || mr1 > m1)) {
            float mn0 = fmaxf(m0, mr0), mn1 = fmaxf(m1, mr1);
            float f0 = exp2p((m0 - mn0) * CEXP);
            float f1 = exp2p((m1 - mn1) * CEXP);
            l0 *= f0; l1 *= f1;
            #pragma unroll
            for (int nf = 0; nf < 8; nf++) {
                o[nf][0] *= f0; o[nf][1] *= f0; o[nf][2] *= f1; o[nf][3] *= f1;
            }
            m0 = mn0; m1 = mn1;
        }
        #pragma unroll
        for (int nf = 0; nf < 8; nf++) {
            s[nf][0] = exp2p((s[nf][0] - m0) * CEXP);
            s[nf][1] = exp2p((s[nf][1] - m0) * CEXP);
            s[nf][2] = exp2p((s[nf][2] - m1) * CEXP);
            s[nf][3] = exp2p((s[nf][3] - m1) * CEXP);
            l0 += s[nf][0] + s[nf][1];
            l1 += s[nf][2] + s[nf][3];
        }

        #pragma unroll
        for (int kk = 0; kk < 4; kk++) {
            uint32_t p0 = packh2(s[2*kk][0],   s[2*kk][1]);
            uint32_t p1 = packh2(s[2*kk][2],   s[2*kk][3]);
            uint32_t p2 = packh2(s[2*kk+1][0], s[2*kk+1][1]);
            uint32_t p3 = packh2(s[2*kk+1][2], s[2*kk+1][3]);
            #pragma unroll
            for (int ep = 0; ep < 4; ep++) {
                uint32_t vh[4];
                ldsm_x4t(sV + voff[kk][ep], vh);
                mma_f16(o[2*ep],   p0, p1, p2, p3, vh[0], vh[2]);
                mma_f16(o[2*ep+1], p0, p1, p2, p3, vh[1], vh[3]);
            }
        }
    }

    l0 += __shfl_xor_sync(0xffffffffu, l0, 1);
    l0 += __shfl_xor_sync(0xffffffffu, l0, 2);
    l1 += __shfl_xor_sync(0xffffffffu, l1, 1);
    l1 += __shfl_xor_sync(0xffffffffu, l1, 2);
    float rl0 = 1.0f / l0, rl1 = 1.0f / l1;
    int row0 = qstart + w * 16 + (lane >> 2);
    size_t ob0 = ((size_t)(b * SEQ + row0)) * DM + h * 64;
    size_t ob1 = ob0 + (size_t)8 * DM;
    #pragma unroll
    for (int nf = 0; nf < 8; nf++) {
        int e = nf * 8 + (lane & 3) * 2;
        *(uint32_t*)(O + ob0 + e) = packh2(o[nf][0] * rl0, o[nf][1] * rl0);
        *(uint32_t*)(O + ob1 + e) = packh2(o[nf][2] * rl1, o[nf][3] * rl1);
    }
}

// ---------------- launch ----------------
extern "C" void kernel_launch(void* const* d_in, const int* in_sizes, int n_in,
                              void* d_out, int out_size) {
    const float* x      = (const float*)d_in[0];
    const float* gamma1 = (const float*)d_in[1];
    const float* beta1  = (const float*)d_in[2];
    const float* wq     = (const float*)d_in[3];
    const float* wk     = (const float*)d_in[4];
    const float* wv     = (const float*)d_in[5];
    const float* wo     = (const float*)d_in[6];
    const float* gamma2 = (const float*)d_in[7];
    const float* beta2  = (const float*)d_in[8];
    const float* fc1    = (const float*)d_in[9];
    const float* fc2    = (const float*)d_in[10];
    float* out = (float*)d_out;

    float *resid_;
    __half *n_, *qkv_, *a_, *h_, *w_;
    cudaGetSymbolAddress((void**)&resid_, g_resid);
    cudaGetSymbolAddress((void**)&n_,   g_n);
    cudaGetSymbolAddress((void**)&qkv_, g_qkv);
    cudaGetSymbolAddress((void**)&a_,   g_a);
    cudaGetSymbolAddress((void**)&h_,   g_h);
    cudaGetSymbolAddress((void**)&w_,   g_w);

    cudaFuncSetAttribute(gemm_tc<0,2>, cudaFuncAttributeMaxDynamicSharedMemorySize, GSM);
    cudaFuncSetAttribute(gemm_tc<1,0>, cudaFuncAttributeMaxDynamicSharedMemorySize, GSM);
    cudaFuncSetAttribute(gemm_tc<2,2>, cudaFuncAttributeMaxDynamicSharedMemorySize, GSM);
    cudaFuncSetAttribute(flash_attn_tc, cudaFuncAttributeMaxDynamicSharedMemorySize, ASM);

    conv_all<<<3145728 / 1024, 256>>>(wq, wk, wv, wo, fc1, fc2, w_);

    dim3 gQKV(QKVS / 128, BS / 256);     // (24, 32)
    dim3 gProj(DM / 128, BS / 256);      // (8, 32)
    dim3 gFF1(DFF / 128, BS / 256);      // (32, 32)
    dim3 gFF2(DM / 128, BS / 256);       // (8, 32)
    dim3 gAttn(SEQ / 64, BATCH * NH);    // (32, 64)

    layernorm_k<<<BS, 256>>>(x, gamma1, beta1, n_);
    gemm_tc<0,2><<<gQKV, 512, GSM>>>(n_, w_ + WOFF_Q, nullptr, nullptr, qkv_, BS, QKVS, DM);
    flash_attn_tc<<<gAttn, 128, ASM>>>(qkv_, a_);
    gemm_tc<1,0><<<gProj, 512, GSM>>>(a_, w_ + WOFF_O, x, resid_, nullptr, BS, DM, DM);
    layernorm_k<<<BS, 256>>>(resid_, gamma2, beta2, n_);
    gemm_tc<2,2><<<gFF1, 512, GSM>>>(n_, w_ + WOFF_F1, nullptr, nullptr, h_, BS, DFF, DM);
    gemm_tc<1,0><<<gFF2, 512, GSM>>>(h_, w_ + WOFF_F2, resid_, out, nullptr, BS, DM, DFF);
}

// round 16
// speedup vs baseline: 1.0336x; 1.0336x over previous
#include <cuda_runtime.h>
#include <cuda_fp16.h>
#include <math.h>
#include <stdint.h>

#define BATCH 4
#define SEQ   2048
#define DM    1024
#define NH    16
#define DH    64
#define DFF   4096
#define BS    (BATCH*SEQ)
#define QKVS  3072
#define EPSLN 1e-5f
#define CEXP  0.1803368801f   // log2(e)/8

// ---------------- scratch ----------------
__device__ float g_resid[(size_t)BS*DM];
__device__ __half g_n[(size_t)BS*DM];
__device__ __half g_qkv[(size_t)BS*QKVS];
__device__ __half g_a[(size_t)BS*DM];
__device__ __half g_h[(size_t)BS*DFF];
#define WOFF_Q  ((size_t)0)
#define WOFF_K  ((size_t)DM*DM)
#define WOFF_V  ((size_t)2*DM*DM)
#define WOFF_O  ((size_t)3*DM*DM)
#define WOFF_F1 ((size_t)4*DM*DM)
#define WOFF_F2 ((size_t)(4*DM*DM) + (size_t)DFF*DM)
__device__ __half g_w[(size_t)4*DM*DM + 2*(size_t)DFF*DM];

// ---------------- helpers ----------------
__device__ __forceinline__ uint32_t smem_u32(const void* p) {
    uint32_t a;
    asm("{ .reg .u64 t; cvta.to.shared.u64 t, %1; cvt.u32.u64 %0, t; }" : "=r"(a) : "l"(p));
    return a;
}
__device__ __forceinline__ uint32_t swz128(uint32_t off) { return off ^ ((off >> 3) & 0x70); }

__device__ __forceinline__ void ldsm_x4(uint32_t addr, uint32_t& r0, uint32_t& r1,
                                        uint32_t& r2, uint32_t& r3) {
    asm volatile("ldmatrix.sync.aligned.m8n8.x4.shared.b16 {%0,%1,%2,%3}, [%4];"
                 : "=r"(r0), "=r"(r1), "=r"(r2), "=r"(r3) : "r"(addr));
}
__device__ __forceinline__ void ldsm_x4t(uint32_t addr, uint32_t* r) {
    asm volatile("ldmatrix.sync.aligned.m8n8.x4.trans.shared.b16 {%0,%1,%2,%3}, [%4];"
                 : "=r"(r[0]), "=r"(r[1]), "=r"(r[2]), "=r"(r[3]) : "r"(addr));
}
__device__ __forceinline__ void mma_f16(float* d, uint32_t a0, uint32_t a1,
                                        uint32_t a2, uint32_t a3,
                                        uint32_t b0, uint32_t b1) {
    asm volatile("mma.sync.aligned.m16n8k16.row.col.f32.f16.f16.f32 "
                 "{%0,%1,%2,%3}, {%4,%5,%6,%7}, {%8,%9}, {%0,%1,%2,%3};"
                 : "+f"(d[0]), "+f"(d[1]), "+f"(d[2]), "+f"(d[3])
                 : "r"(a0), "r"(a1), "r"(a2), "r"(a3), "r"(b0), "r"(b1));
}
#define CPA(dst, src) asm volatile("cp.async.cg.shared.global [%0], [%1], 16;" :: "r"(dst), "l"(src))

__device__ __forceinline__ float gelu_f(float x) {
    float c = x * x * x;
    float t = tanhf(0.7978845608f * (x + 0.044715f * c));
    return 0.5f * x * (1.0f + t);
}
__device__ __forceinline__ uint32_t packh2(float x, float y) {
    __half2 h = __floats2half2_rn(x, y);
    return *reinterpret_cast<uint32_t*>(&h);
}
__device__ __forceinline__ float exp2p(float x) {
    x = fmaxf(x, -60.0f);
    float y = x + 12582912.0f;
    int   n = __float_as_int(y) - 0x4B400000;
    float f = x - (y - 12582912.0f);
    float p =            1.3333558e-3f;
    p = fmaf(p, f, 9.6181291e-3f);
    p = fmaf(p, f, 5.5504109e-2f);
    p = fmaf(p, f, 2.4022651e-1f);
    p = fmaf(p, f, 6.9314718e-1f);
    p = fmaf(p, f, 1.0f);
    return __uint_as_float(__float_as_uint(p) + ((uint32_t)n << 23));
}

// ---------------- fused weight convert (4 float4 per thread) ----------------
__global__ __launch_bounds__(256)
void conv_all(const float* __restrict__ wq, const float* __restrict__ wk,
              const float* __restrict__ wv, const float* __restrict__ wo,
              const float* __restrict__ f1, const float* __restrict__ f2,
              __half* __restrict__ w) {
    int base = (blockIdx.x * 256 + threadIdx.x) * 4;
    float4 v[4];
    #pragma unroll
    for (int j = 0; j < 4; j++) {
        int i = base + j;
        const float* src;
        int loc;
        if (i < (1 << 20)) {
            int r = i >> 18;
            loc = i & ((1 << 18) - 1);
            src = (r == 0) ? wq : (r == 1) ? wk : (r == 2) ? wv : wo;
        } else {
            int jj = i - (1 << 20);
            if (jj < (1 << 20)) { src = f1; loc = jj; }
            else                { src = f2; loc = jj - (1 << 20); }
        }
        v[j] = *(const float4*)(src + (size_t)loc * 4);
    }
    #pragma unroll
    for (int j = 0; j < 4; j++) {
        uint2 o;
        o.x = packh2(v[j].x, v[j].y);
        o.y = packh2(v[j].z, v[j].w);
        *(uint2*)(w + (size_t)(base + j) * 4) = o;
    }
}

// ---------------- layernorm -> f16 ----------------
__global__ __launch_bounds__(256)
void layernorm_k(const float* __restrict__ x, const float* __restrict__ gamma,
                 const float* __restrict__ beta, __half* __restrict__ oh) {
    int row = blockIdx.x;
    const float* xr = x + (size_t)row * DM;
    int t = threadIdx.x;
    float4 v = *(const float4*)(xr + t * 4);
    float s  = v.x + v.y + v.z + v.w;
    float ss = v.x*v.x + v.y*v.y + v.z*v.z + v.w*v.w;
    #pragma unroll
    for (int o = 16; o > 0; o >>= 1) {
        s  += __shfl_xor_sync(0xffffffffu, s,  o);
        ss += __shfl_xor_sync(0xffffffffu, ss, o);
    }
    __shared__ float rs[8], rss[8];
    int w = t >> 5, l = t & 31;
    if (l == 0) { rs[w] = s; rss[w] = ss; }
    __syncthreads();
    if (w == 0) {
        float a = (l < 8) ? rs[l]  : 0.f;
        float b = (l < 8) ? rss[l] : 0.f;
        #pragma unroll
        for (int o = 4; o > 0; o >>= 1) {
            a += __shfl_xor_sync(0xffffffffu, a, o);
            b += __shfl_xor_sync(0xffffffffu, b, o);
        }
        if (l == 0) { rs[0] = a; rss[0] = b; }
    }
    __syncthreads();
    float mean = rs[0] * (1.0f / DM);
    float var  = rss[0] * (1.0f / DM) - mean * mean;
    float rstd = rsqrtf(var + EPSLN);
    float4 gv = *(const float4*)(gamma + t * 4);
    float4 bv = *(const float4*)(beta  + t * 4);
    uint2 o2;
    o2.x = packh2(gv.x * ((v.x - mean) * rstd) + bv.x,
                  gv.y * ((v.y - mean) * rstd) + bv.y);
    o2.y = packh2(gv.z * ((v.z - mean) * rstd) + bv.z,
                  gv.w * ((v.w - mean) * rstd) + bv.w);
    *(uint2*)(oh + (size_t)row * DM + t * 4) = o2;
}

// ---------------- fp16 GEMM NT: 128x128x64, 4 warps (2x2), 64x64 warp tiles ----------------
// 128 threads, 2 CTAs/SM. Per kseg: 4 A-ldsm + 4 B-ldsm -> 32 MMAs (128 B/MMA).
#define GSM (3*32768 + 1024)

template<int EPI, int OUT>
__global__ __launch_bounds__(128, 2)
void gemm_tc(const __half* __restrict__ A_, const __half* __restrict__ W_,
             const float* __restrict__ R, float* __restrict__ Cf,
             __half* __restrict__ Ch, int M, int N, int K) {
    extern __shared__ char dsm[];
    uint32_t sb = (smem_u32(dsm) + 1023) & ~1023u;

    int tid = threadIdx.x, wid = tid >> 5, lane = tid & 31;
    int wm = wid >> 1, wn = wid & 1;           // warp tile: rows wm*64, cols wn*64

    const char* Ab = (const char*)(A_ + (size_t)blockIdx.y * 128 * K);
    const char* Wb = (const char*)(W_ + (size_t)blockIdx.x * 128 * K);

    // copy: 128 threads, 8 granules of 16B per matrix per chunk
    int cs = tid & 7;
    int rbase = tid >> 3;                      // 0..15
    uint32_t soA[8];
    size_t gbA[8];
    #pragma unroll
    for (int i = 0; i < 8; i++) {
        int row = rbase + 16 * i;
        soA[i] = swz128(row * 128 + cs * 16);
        gbA[i] = (size_t)row * K * 2 + cs * 16;
    }

    #define G_ISSUE(kb, st) do { \
        uint32_t s_ = sb + (st) * 32768; \
        size_t kbb = (size_t)(kb) * 2; \
        _Pragma("unroll") \
        for (int i_ = 0; i_ < 8; i_++) { \
            CPA(s_ + soA[i_],         Ab + gbA[i_] + kbb); \
            CPA(s_ + 16384 + soA[i_], Wb + gbA[i_] + kbb); \
        } \
    } while (0)

    float acc[4][8][4];
    #pragma unroll
    for (int i = 0; i < 4; i++)
        #pragma unroll
        for (int j = 0; j < 8; j++)
            #pragma unroll
            for (int e = 0; e < 4; e++) acc[i][j][e] = 0.f;

    int g = lane >> 3, rg = lane & 7;
    int nch = K >> 6;

    G_ISSUE(0, 0);
    asm volatile("cp.async.commit_group;");
    G_ISSUE(64, 1);
    asm volatile("cp.async.commit_group;");

    int st_c = 0, st_i = 2;
    for (int ch = 0; ch < nch; ch++) {
        if (ch + 1 < nch) asm volatile("cp.async.wait_group 1;" ::: "memory");
        else              asm volatile("cp.async.wait_group 0;" ::: "memory");
        __syncthreads();
        if (ch + 2 < nch) {
            G_ISSUE((ch + 2) << 6, st_i);
            asm volatile("cp.async.commit_group;");
            st_i = (st_i == 2) ? 0 : st_i + 1;
        }
        uint32_t ah = sb + st_c * 32768;
        st_c = (st_c == 2) ? 0 : st_c + 1;
        uint32_t bh = ah + 16384;

        #pragma unroll
        for (int ks = 0; ks < 4; ks++) {
            int kcol = ks * 32 + (g >> 1) * 16;
            uint32_t bhr[4][4];
            #pragma unroll
            for (int p = 0; p < 4; p++) {
                int nrow = wn * 64 + p * 16 + (g & 1) * 8 + rg;
                uint32_t off = swz128(nrow * 128 + kcol);
                ldsm_x4(bh + off, bhr[p][0], bhr[p][1], bhr[p][2], bhr[p][3]);
            }
            #pragma unroll
            for (int mf = 0; mf < 4; mf++) {
                int arow = wm * 64 + mf * 16 + (g & 1) * 8 + rg;
                uint32_t off = swz128(arow * 128 + kcol);
                uint32_t a0,a1,a2,a3;
                ldsm_x4(ah + off, a0, a1, a2, a3);
                #pragma unroll
                for (int nf = 0; nf < 8; nf++) {
                    int p = nf >> 1, q = nf & 1;
                    mma_f16(acc[mf][nf], a0, a1, a2, a3, bhr[p][q], bhr[p][q + 2]);
                }
            }
        }
    }

    #pragma unroll
    for (int mf = 0; mf < 4; mf++) {
        #pragma unroll
        for (int h = 0; h < 2; h++) {
            size_t row = (size_t)blockIdx.y * 128 + wm * 64 + mf * 16 + (lane >> 2) + h * 8;
            #pragma unroll
            for (int nf = 0; nf < 8; nf++) {
                size_t col = (size_t)blockIdx.x * 128 + wn * 64 + nf * 8 + (lane & 3) * 2;
                float o0 = acc[mf][nf][h * 2 + 0];
                float o1 = acc[mf][nf][h * 2 + 1];
                if (EPI == 1) {
                    float2 r2 = *(const float2*)(R + row * N + col);
                    o0 += r2.x; o1 += r2.y;
                }
                if (EPI == 2) { o0 = gelu_f(o0); o1 = gelu_f(o1); }
                if (OUT == 0) {
                    *(float2*)(Cf + row * N + col) = make_float2(o0, o1);
                } else {
                    *(uint32_t*)(Ch + row * N + col) = packh2(o0, o1);
                }
            }
        }
    }
}

// ---------------- fp16 flash attention (R14: 64-row Q tile, hoisted offsets) ----------------
#define ASM (8192 + 3*16384 + 1024)

__global__ __launch_bounds__(128)
void flash_attn_tc(const __half* __restrict__ QKV, __half* __restrict__ O) {
    extern __shared__ char dsm[];
    uint32_t sb = (smem_u32(dsm) + 1023) & ~1023u;
    uint32_t sQ = sb;

    int qt = gridDim.x - 1 - blockIdx.x;
    int bh = blockIdx.y;
    int b = bh >> 4, h = bh & 15;
    int tid = threadIdx.x, w = tid >> 5, lane = tid & 31;
    int g = lane >> 3, rg = lane & 7;
    int qstart = qt * 64;

    const char* Qc = (const char*)QKV;

    size_t qg = ((size_t)(b * SEQ + qstart)) * QKVS + h * 64;
    #pragma unroll
    for (int i = 0; i < 4; i++) {
        int seg = tid + i * 128;
        int row = seg >> 3, cs = seg & 7;
        uint32_t so = swz128(row * 128 + cs * 16);
        size_t gb = (qg + (size_t)row * QKVS + cs * 8) * 2;
        CPA(sQ + so, Qc + gb);
    }

    #define AKV_ISSUE(kbase, st) do { \
        uint32_t s_ = sb + 8192 + (st) * 16384; \
        size_t g0 = ((size_t)(b * SEQ + (kbase))) * QKVS + 1024 + h * 64; \
        _Pragma("unroll") \
        for (int i_ = 0; i_ < 4; i_++) { \
            int seg_ = tid + i_ * 128; \
            int row_ = seg_ >> 3, cs_ = seg_ & 7; \
            uint32_t so_ = swz128(row_ * 128 + cs_ * 16); \
            size_t gb_ = (g0 + (size_t)row_ * QKVS + cs_ * 8) * 2; \
            CPA(s_ + so_,        Qc + gb_); \
            CPA(s_ + 8192 + so_, Qc + gb_ + 2048); \
        } \
    } while (0)

    AKV_ISSUE(0, 0);
    asm volatile("cp.async.commit_group;");
    if (qt >= 1) {
        AKV_ISSUE(64, 1);
        asm volatile("cp.async.commit_group;");
    }

    uint32_t koff[4][4], voff[4][4];
    #pragma unroll
    for (int kseg = 0; kseg < 4; kseg++) {
        int kcol = kseg * 32 + (g >> 1) * 16;
        #pragma unroll
        for (int p = 0; p < 4; p++) {
            int nrow = p * 16 + (g & 1) * 8 + rg;
            koff[kseg][p] = swz128(nrow * 128 + kcol);
        }
    }
    #pragma unroll
    for (int kk = 0; kk < 4; kk++) {
        int vrow = kk * 16 + (g >> 1) * 8 + rg;
        #pragma unroll
        for (int ep = 0; ep < 4; ep++) {
            int ecol = ep * 16 + (g & 1) * 8;
            voff[kk][ep] = swz128(vrow * 128 + ecol * 2);
        }
    }

    float s[8][4], o[8][4];
    uint32_t qf[4][4];
    #pragma unroll
    for (int nf = 0; nf < 8; nf++)
        #pragma unroll
        for (int e = 0; e < 4; e++) o[nf][e] = 0.f;
    float m0 = -1e30f, m1 = -1e30f, l0 = 0.f, l1 = 0.f;

    int st_c = 0, st_i = 2;
    for (int kb = 0; kb <= qt; kb++) {
        if (kb < qt) asm volatile("cp.async.wait_group 1;" ::: "memory");
        else         asm volatile("cp.async.wait_group 0;" ::: "memory");
        __syncthreads();
        if (kb + 2 <= qt) {
            AKV_ISSUE((kb + 2) * 64, st_i);
            asm volatile("cp.async.commit_group;");
            st_i = (st_i == 2) ? 0 : st_i + 1;
        }

        if (kb == 0) {
            #pragma unroll
            for (int kseg = 0; kseg < 4; kseg++) {
                int arow = w * 16 + (g & 1) * 8 + rg;
                uint32_t off = swz128(arow * 128 + kseg * 32 + (g >> 1) * 16);
                ldsm_x4(sQ + off, qf[kseg][0], qf[kseg][1], qf[kseg][2], qf[kseg][3]);
            }
        }

        uint32_t kB = sb + 8192 + st_c * 16384;
        st_c = (st_c == 2) ? 0 : st_c + 1;
        uint32_t sK = kB, sV = kB + 8192;

        #pragma unroll
        for (int nf = 0; nf < 8; nf++)
            #pragma unroll
            for (int e = 0; e < 4; e++) s[nf][e] = 0.f;
        #pragma unroll
        for (int kseg = 0; kseg < 4; kseg++) {
            uint32_t kh[4][4];
            #pragma unroll
            for (int p = 0; p < 4; p++)
                ldsm_x4(sK + koff[kseg][p], kh[p][0], kh[p][1], kh[p][2], kh[p][3]);
            #pragma unroll
            for (int p = 0; p < 4; p++)
                #pragma unroll
                for (int q = 0; q < 2; q++)
                    mma_f16(s[2*p+q], qf[kseg][0], qf[kseg][1], qf[kseg][2], qf[kseg][3],
                            kh[p][q], kh[p][q + 2]);
        }

        if (kb == qt) {
            int r0 = w * 16 + (lane >> 2);
            int c0 = (lane & 3) * 2;
            #pragma unroll
            for (int nf = 0; nf < 8; nf++) {
                int c = c0 + nf * 8;
                if (c     > r0)     s[nf][0] = -1e30f;
                if (c + 1 > r0)     s[nf][1] = -1e30f;
                if (c     > r0 + 8) s[nf][2] = -1e30f;
                if (c + 1 > r0 + 8) s[nf][3] = -1e30f;
            }
        }

        float mr0 = -1e30f, mr1 = -1e30f;
        #pragma unroll
        for (int nf = 0; nf < 8; nf++) {
            mr0 = fmaxf(mr0, fmaxf(s[nf][0], s[nf][1]));
            mr1 = fmaxf(mr1, fmaxf(s[nf][2], s[nf][3]));
        }
        mr0 = fmaxf(mr0, __shfl_xor_sync(0xffffffffu, mr0, 1));
        mr0 = fmaxf(mr0, __shfl_xor_sync(0xffffffffu, mr0, 2));
        mr1 = fmaxf(mr1, __shfl_xor_sync(0xffffffffu, mr1, 1));
        mr1 = fmaxf(mr1, __shfl_xor_sync(0xffffffffu, mr1, 2));
        if (__any_sync(0xffffffffu, mr0 > m0 || mr1 > m1)) {
            float mn0 = fmaxf(m0, mr0), mn1 = fmaxf(m1, mr1);
            float f0 = exp2p((m0 - mn0) * CEXP);
            float f1 = exp2p((m1 - mn1) * CEXP);
            l0 *= f0; l1 *= f1;
            #pragma unroll
            for (int nf = 0; nf < 8; nf++) {
                o[nf][0] *= f0; o[nf][1] *= f0; o[nf][2] *= f1; o[nf][3] *= f1;
            }
            m0 = mn0; m1 = mn1;
        }
        #pragma unroll
        for (int nf = 0; nf < 8; nf++) {
            s[nf][0] = exp2p((s[nf][0] - m0) * CEXP);
            s[nf][1] = exp2p((s[nf][1] - m0) * CEXP);
            s[nf][2] = exp2p((s[nf][2] - m1) * CEXP);
            s[nf][3] = exp2p((s[nf][3] - m1) * CEXP);
            l0 += s[nf][0] + s[nf][1];
            l1 += s[nf][2] + s[nf][3];
        }

        #pragma unroll
        for (int kk = 0; kk < 4; kk++) {
            uint32_t p0 = packh2(s[2*kk][0],   s[2*kk][1]);
            uint32_t p1 = packh2(s[2*kk][2],   s[2*kk][3]);
            uint32_t p2 = packh2(s[2*kk+1][0], s[2*kk+1][1]);
            uint32_t p3 = packh2(s[2*kk+1][2], s[2*kk+1][3]);
            #pragma unroll
            for (int ep = 0; ep < 4; ep++) {
                uint32_t vh[4];
                ldsm_x4t(sV + voff[kk][ep], vh);
                mma_f16(o[2*ep],   p0, p1, p2, p3, vh[0], vh[2]);
                mma_f16(o[2*ep+1], p0, p1, p2, p3, vh[1], vh[3]);
            }
        }
    }

    l0 += __shfl_xor_sync(0xffffffffu, l0, 1);
    l0 += __shfl_xor_sync(0xffffffffu, l0, 2);
    l1 += __shfl_xor_sync(0xffffffffu, l1, 1);
    l1 += __shfl_xor_sync(0xffffffffu, l1, 2);
    float rl0 = 1.0f / l0, rl1 = 1.0f / l1;
    int row0 = qstart + w * 16 + (lane >> 2);
    size_t ob0 = ((size_t)(b * SEQ + row0)) * DM + h * 64;
    size_t ob1 = ob0 + (size_t)8 * DM;
    #pragma unroll
    for (int nf = 0; nf < 8; nf++) {
        int e = nf * 8 + (lane & 3) * 2;
        *(uint32_t*)(O + ob0 + e) = packh2(o[nf][0] * rl0, o[nf][1] * rl0);
        *(uint32_t*)(O + ob1 + e) = packh2(o[nf][2] * rl1, o[nf][3] * rl1);
    }
}

// ---------------- launch ----------------
extern "C" void kernel_launch(void* const* d_in, const int* in_sizes, int n_in,
                              void* d_out, int out_size) {
    const float* x      = (const float*)d_in[0];
    const float* gamma1 = (const float*)d_in[1];
    const float* beta1  = (const float*)d_in[2];
    const float* wq     = (const float*)d_in[3];
    const float* wk     = (const float*)d_in[4];
    const float* wv     = (const float*)d_in[5];
    const float* wo     = (const float*)d_in[6];
    const float* gamma2 = (const float*)d_in[7];
    const float* beta2  = (const float*)d_in[8];
    const float* fc1    = (const float*)d_in[9];
    const float* fc2    = (const float*)d_in[10];
    float* out = (float*)d_out;

    float *resid_;
    __half *n_, *qkv_, *a_, *h_, *w_;
    cudaGetSymbolAddress((void**)&resid_, g_resid);
    cudaGetSymbolAddress((void**)&n_,   g_n);
    cudaGetSymbolAddress((void**)&qkv_, g_qkv);
    cudaGetSymbolAddress((void**)&a_,   g_a);
    cudaGetSymbolAddress((void**)&h_,   g_h);
    cudaGetSymbolAddress((void**)&w_,   g_w);

    cudaFuncSetAttribute(gemm_tc<0,2>, cudaFuncAttributeMaxDynamicSharedMemorySize, GSM);
    cudaFuncSetAttribute(gemm_tc<1,0>, cudaFuncAttributeMaxDynamicSharedMemorySize, GSM);
    cudaFuncSetAttribute(gemm_tc<2,2>, cudaFuncAttributeMaxDynamicSharedMemorySize, GSM);
    cudaFuncSetAttribute(flash_attn_tc, cudaFuncAttributeMaxDynamicSharedMemorySize, ASM);

    conv_all<<<3145728 / 1024, 256>>>(wq, wk, wv, wo, fc1, fc2, w_);

    dim3 gQKV(QKVS / 128, BS / 128);     // (24, 64)
    dim3 gProj(DM / 128, BS / 128);      // (8, 64)
    dim3 gFF1(DFF / 128, BS / 128);      // (32, 64)
    dim3 gFF2(DM / 128, BS / 128);       // (8, 64)
    dim3 gAttn(SEQ / 64, BATCH * NH);    // (32, 64)

    layernorm_k<<<BS, 256>>>(x, gamma1, beta1, n_);
    gemm_tc<0,2><<<gQKV, 128, GSM>>>(n_, w_ + WOFF_Q, nullptr, nullptr, qkv_, BS, QKVS, DM);
    flash_attn_tc<<<gAttn, 128, ASM>>>(qkv_, a_);
    gemm_tc<1,0><<<gProj, 128, GSM>>>(a_, w_ + WOFF_O, x, resid_, nullptr, BS, DM, DM);
    layernorm_k<<<BS, 256>>>(resid_, gamma2, beta2, n_);
    gemm_tc<2,2><<<gFF1, 128, GSM>>>(n_, w_ + WOFF_F1, nullptr, nullptr, h_, BS, DFF, DM);
    gemm_tc<1,0><<<gFF2, 128, GSM>>>(h_, w_ + WOFF_F2, resid_, out, nullptr, BS, DM, DFF);
}